// round 4
// baseline (speedup 1.0000x reference)
#include <cuda_runtime.h>
#include <cstdint>

#define BB 32
#define NN 512
#define HH 128
constexpr float LN_EPS = 1e-5f;

// h transposed: h_T[b][d][j]  (B, H, N) fp32, 8 MB
__device__ float g_hT[(size_t)BB * HH * NN];

// ---------------------------------------------------------------------------
// helpers
// ---------------------------------------------------------------------------
__device__ __forceinline__ uint32_t f2tf32(float x) {
    uint32_t r;
    asm("cvt.rna.tf32.f32 %0, %1;" : "=r"(r) : "f"(x));
    return r;
}

__device__ __forceinline__ uint32_t smem_u32(const void* p) {
    uint32_t a;
    asm("{ .reg .u64 t; cvta.to.shared.u64 t, %1; cvt.u32.u64 %0, t; }"
        : "=r"(a) : "l"(p));
    return a;
}

__device__ __forceinline__ void mma_sync_tf32(float* d, const uint32_t* a, const uint32_t* b) {
    asm volatile(
        "mma.sync.aligned.m16n8k8.row.col.f32.tf32.tf32.f32 "
        "{%0,%1,%2,%3}, {%4,%5,%6,%7}, {%8,%9}, {%0,%1,%2,%3};\n"
        : "+f"(d[0]), "+f"(d[1]), "+f"(d[2]), "+f"(d[3])
        : "r"(a[0]), "r"(a[1]), "r"(a[2]), "r"(a[3]), "r"(b[0]), "r"(b[1]));
}

__device__ __forceinline__ void ldm4(uint32_t* r, uint32_t saddr) {
    asm volatile(
        "ldmatrix.sync.aligned.m8n8.x4.shared.b16 {%0,%1,%2,%3}, [%4];"
        : "=r"(r[0]), "=r"(r[1]), "=r"(r[2]), "=r"(r[3])
        : "r"(saddr));
}

// ---------------------------------------------------------------------------
// Stage 1: h = silu(layernorm(s @ W1^T + b1)), stored TRANSPOSED to g_hT[b][d][j]
// ---------------------------------------------------------------------------
__global__ __launch_bounds__(256) void lin1_ln_silu_kernel(
    const float* __restrict__ s, const float* __restrict__ W1,
    const float* __restrict__ b1)
{
    __shared__ float smem[64 * 133];  // Hs[64][133]; phase A uses first 6912 as As/Bs
    float* As = smem;                 // [64][36]
    float* Bs = smem + 64 * 36;       // [128][36]
    float* Hs = smem;                 // [64][133]

    const int tid  = threadIdx.x;
    const int r0   = blockIdx.x * 64;
    const int w    = tid >> 5;
    const int lane = tid & 31;
    const int g    = lane >> 2;
    const int tg   = lane & 3;
    const int wm   = w & 1;
    const int wn   = w >> 1;

    float acc[2][4][4];
    #pragma unroll
    for (int i = 0; i < 2; i++)
        #pragma unroll
        for (int j = 0; j < 4; j++)
            #pragma unroll
            for (int k = 0; k < 4; k++) acc[i][j][k] = 0.f;

    const uint32_t* A32 = (const uint32_t*)As;
    const uint32_t* B32 = (const uint32_t*)Bs;

    for (int kc = 0; kc < 4; kc++) {
        const int k0 = kc * 32;
        __syncthreads();
        #pragma unroll
        for (int it = 0; it < 2; it++) {
            int idx = tid + it * 256;
            int row = idx >> 3, q = idx & 7;
            float4 v = *(const float4*)(s + (size_t)(r0 + row) * HH + k0 + q * 4);
            uint32_t* dst = (uint32_t*)(As + row * 36 + q * 4);
            dst[0] = f2tf32(v.x); dst[1] = f2tf32(v.y);
            dst[2] = f2tf32(v.z); dst[3] = f2tf32(v.w);
        }
        #pragma unroll
        for (int it = 0; it < 4; it++) {
            int idx = tid + it * 256;
            int n = idx >> 3, q = idx & 7;
            float4 v = *(const float4*)(W1 + (size_t)n * HH + k0 + q * 4);
            uint32_t* dst = (uint32_t*)(Bs + n * 36 + q * 4);
            dst[0] = f2tf32(v.x); dst[1] = f2tf32(v.y);
            dst[2] = f2tf32(v.z); dst[3] = f2tf32(v.w);
        }
        __syncthreads();
        #pragma unroll
        for (int ks = 0; ks < 4; ks++) {
            const int kk = ks * 8;
            uint32_t af[2][4], bf[4][2];
            #pragma unroll
            for (int mt = 0; mt < 2; mt++) {
                int rm = wm * 32 + mt * 16;
                af[mt][0] = A32[(rm + g) * 36 + kk + tg];
                af[mt][1] = A32[(rm + g + 8) * 36 + kk + tg];
                af[mt][2] = A32[(rm + g) * 36 + kk + tg + 4];
                af[mt][3] = A32[(rm + g + 8) * 36 + kk + tg + 4];
            }
            #pragma unroll
            for (int nt = 0; nt < 4; nt++) {
                int cn = wn * 32 + nt * 8 + g;
                bf[nt][0] = B32[cn * 36 + kk + tg];
                bf[nt][1] = B32[cn * 36 + kk + tg + 4];
            }
            #pragma unroll
            for (int mt = 0; mt < 2; mt++)
                #pragma unroll
                for (int nt = 0; nt < 4; nt++)
                    mma_sync_tf32(acc[mt][nt], af[mt], bf[nt]);
        }
    }

    __syncthreads();
    #pragma unroll
    for (int mt = 0; mt < 2; mt++) {
        #pragma unroll
        for (int nt = 0; nt < 4; nt++) {
            int rm = wm * 32 + mt * 16 + g;
            int cn = wn * 32 + nt * 8 + 2 * tg;
            Hs[rm * 133 + cn]           = acc[mt][nt][0];
            Hs[rm * 133 + cn + 1]       = acc[mt][nt][1];
            Hs[(rm + 8) * 133 + cn]     = acc[mt][nt][2];
            Hs[(rm + 8) * 133 + cn + 1] = acc[mt][nt][3];
        }
    }
    __syncthreads();

    // LayerNorm + SiLU, write back into Hs
    #pragma unroll
    for (int rr = 0; rr < 8; rr++) {
        int row = w * 8 + rr;
        float x[4];
        float sum = 0.f, sq = 0.f;
        #pragma unroll
        for (int k = 0; k < 4; k++) {
            float v = Hs[row * 133 + lane + 32 * k] + __ldg(b1 + lane + 32 * k);
            x[k] = v; sum += v; sq += v * v;
        }
        #pragma unroll
        for (int o = 16; o > 0; o >>= 1) {
            sum += __shfl_xor_sync(0xffffffffu, sum, o);
            sq  += __shfl_xor_sync(0xffffffffu, sq, o);
        }
        float mu  = sum * (1.f / 128.f);
        float var = sq * (1.f / 128.f) - mu * mu;
        float inv = rsqrtf(var + LN_EPS);
        #pragma unroll
        for (int k = 0; k < 4; k++) {
            float yv = (x[k] - mu) * inv;
            Hs[row * 133 + lane + 32 * k] = yv / (1.f + __expf(-yv));
        }
    }
    __syncthreads();

    // Transposed write-out: g_hT[b][d][n]
    const int b  = r0 >> 9;
    const int n0 = r0 & 511;
    #pragma unroll
    for (int it = 0; it < 8; it++) {
        int idx = tid + it * 256;       // 0..2047
        int d = idx >> 4;               // 0..127
        int q = idx & 15;               // float4 index along 64 j's
        float4 v;
        v.x = Hs[(q * 4 + 0) * 133 + d];
        v.y = Hs[(q * 4 + 1) * 133 + d];
        v.z = Hs[(q * 4 + 2) * 133 + d];
        v.w = Hs[(q * 4 + 3) * 133 + d];
        *(float4*)(g_hT + ((size_t)b * HH + d) * NN + n0 + q * 4) = v;
    }
}

// ---------------------------------------------------------------------------
// Stage 2: mma.sync tf32 GEMM with ldmatrix fragments + double buffering.
// Per block: batch b, m-tile of 128 (m = i*3+c), N=128 (d), K=512 (j), chunks of 32.
// Smem: A[2][128][36] + B[2][128][36] tf32 bits = 72KB dynamic.
// 8 warps, warp tile 64m x 32n: mt=4, nt=4, acc 64 fp32.
// ---------------------------------------------------------------------------
#define ASTRIDE 36
#define TILE_U32 (128 * ASTRIDE)          // 4608
#define SMEM2_BYTES (4 * TILE_U32 * 4)    // 73728

__global__ __launch_bounds__(256, 2)
void cfconv2_kernel(const float* __restrict__ ev,
                    const float* __restrict__ mask,
                    float* __restrict__ out)
{
    extern __shared__ uint32_t sm2[];
    const uint32_t sbase = smem_u32(sm2);

    const int tid  = threadIdx.x;
    const int w    = tid >> 5;
    const int lane = tid & 31;
    const int g    = lane >> 2;
    const int tg   = lane & 3;
    const int wm   = w & 1;        // 2 warp rows (64 m each)
    const int wn   = w >> 1;       // 4 warp cols (32 n each)

    const int b    = blockIdx.y;
    const int m0   = blockIdx.x * 128;
    const int i_lo = m0 / 3;
    const int i_hi = (m0 + 127) / 3;
    const int icnt = i_hi - i_lo + 1;     // <= 44

    // per-lane ldmatrix byte offsets within a tile
    const int arow  = (lane & 7) + ((lane >> 3) & 1) * 8;
    const int ahalf = (lane >> 4) & 1;
    const uint32_t aoff = (uint32_t)(((wm * 64 + arow) * ASTRIDE + ahalf * 4) * 4);
    const int brow  = (lane & 7) + ((lane >> 4) & 1) * 8;
    const int bhalf = (lane >> 3) & 1;
    const uint32_t boff = (uint32_t)(((wn * 32 + brow) * ASTRIDE + bhalf * 4) * 4);

    float acc[4][4][4];
    #pragma unroll
    for (int mt = 0; mt < 4; mt++)
        #pragma unroll
        for (int nt = 0; nt < 4; nt++)
            #pragma unroll
            for (int k = 0; k < 4; k++) acc[mt][nt][k] = 0.f;

    const float* evB   = ev   + (((size_t)b * NN) * NN) * 3;
    const float* maskB = mask + ((size_t)b * NN) * NN;
    const float* hTB   = g_hT + ((size_t)b * HH) * NN;

    // ---- build chunk (j0) into buffer p ----
    auto build = [&](int p, int j0) {
        uint32_t* Ab = sm2 + p * TILE_U32;
        uint32_t* Bb = sm2 + (2 + p) * TILE_U32;
        // B tile: h_T[d][j0..j0+31], 4096 floats
        #pragma unroll
        for (int it = 0; it < 4; it++) {
            int idx = tid + it * 256;
            int d = idx >> 3, q = idx & 7;
            float4 v = *(const float4*)(hTB + (size_t)d * NN + j0 + q * 4);
            uint4 t;
            t.x = f2tf32(v.x); t.y = f2tf32(v.y);
            t.z = f2tf32(v.z); t.w = f2tf32(v.w);
            *(uint4*)(Bb + d * ASTRIDE + q * 4) = t;
        }
        // A tile: mask*ev scattered to [m = i*3+c - m0][j]
        #pragma unroll
        for (int it = 0; it < 5; it++) {
            int idx = tid + it * 256;
            if (idx < icnt * 24) {
                int r = idx / 24;
                int q = idx - r * 24;
                int i = i_lo + r;
                float4 v = *(const float4*)(evB + ((size_t)i * NN + j0) * 3 + q * 4);
                int jc0 = q * 4;
                int ja  = jc0 / 3;
                float mA = __ldg(maskB + (size_t)i * NN + j0 + ja);
                float mB = __ldg(maskB + (size_t)i * NN + j0 + ja + 1);
                float fv[4] = {v.x, v.y, v.z, v.w};
                int mbase = i * 3 - m0;
                #pragma unroll
                for (int e = 0; e < 4; e++) {
                    int jc = jc0 + e;
                    int j  = jc / 3;
                    int c  = jc - 3 * j;
                    int m  = mbase + c;
                    if (m >= 0 && m < 128) {
                        float val = fv[e] * (j == ja ? mA : mB);
                        Ab[m * ASTRIDE + j] = f2tf32(val);
                    }
                }
            }
        }
    };

    build(0, 0);
    __syncthreads();

    for (int ch = 0; ch < 16; ch++) {
        const int p = ch & 1;
        if (ch < 15) build(p ^ 1, (ch + 1) * 32);

        const uint32_t Abase = sbase + (uint32_t)(p * TILE_U32) * 4u;
        const uint32_t Bbase = sbase + (uint32_t)((2 + p) * TILE_U32) * 4u;
        #pragma unroll
        for (int ks = 0; ks < 4; ks++) {
            uint32_t af[4][4], bf[2][4];
            #pragma unroll
            for (int mt = 0; mt < 4; mt++)
                ldm4(af[mt], Abase + aoff + (uint32_t)(mt * 16 * ASTRIDE * 4 + ks * 32));
            #pragma unroll
            for (int bt = 0; bt < 2; bt++)
                ldm4(bf[bt], Bbase + boff + (uint32_t)(bt * 16 * ASTRIDE * 4 + ks * 32));
            #pragma unroll
            for (int mt = 0; mt < 4; mt++)
                #pragma unroll
                for (int nt = 0; nt < 4; nt++)
                    mma_sync_tf32(acc[mt][nt], af[mt], &bf[nt >> 1][(nt & 1) * 2]);
        }
        __syncthreads();
    }

    // Epilogue
    const size_t obase = ((size_t)b * 1536 + m0) * HH;
    #pragma unroll
    for (int mt = 0; mt < 4; mt++) {
        #pragma unroll
        for (int nt = 0; nt < 4; nt++) {
            int m  = wm * 64 + mt * 16 + g;
            int cn = wn * 32 + nt * 8 + 2 * tg;
            *(float2*)(out + obase + (size_t)m * HH + cn) =
                make_float2(acc[mt][nt][0], acc[mt][nt][1]);
            *(float2*)(out + obase + (size_t)(m + 8) * HH + cn) =
                make_float2(acc[mt][nt][2], acc[mt][nt][3]);
        }
    }
}

// ---------------------------------------------------------------------------
// Launch
// ---------------------------------------------------------------------------
extern "C" void kernel_launch(void* const* d_in, const int* in_sizes, int n_in,
                              void* d_out, int out_size) {
    (void)in_sizes; (void)n_in; (void)out_size;
    const float* s    = (const float*)d_in[0];
    const float* ev   = (const float*)d_in[1];
    const float* mask = (const float*)d_in[2];
    const float* W1   = (const float*)d_in[3];
    const float* b1   = (const float*)d_in[4];
    float* out = (float*)d_out;

    static bool attr_set = false;
    if (!attr_set) {
        cudaFuncSetAttribute(cfconv2_kernel,
                             cudaFuncAttributeMaxDynamicSharedMemorySize, SMEM2_BYTES);
        attr_set = true;
    }

    lin1_ln_silu_kernel<<<256, 256>>>(s, W1, b1);
    cfconv2_kernel<<<dim3(12, 32), 256, SMEM2_BYTES>>>(ev, mask, out);
}

// round 5
// speedup vs baseline: 1.6411x; 1.6411x over previous
#include <cuda_runtime.h>
#include <cstdint>

#define BB 32
#define NN 512
#define HH 128
constexpr float LN_EPS = 1e-5f;

// h transposed AND pre-converted to tf32 bits: g_hT[b][d][j]  (B, H, N), 8 MB
__device__ uint32_t g_hT[(size_t)BB * HH * NN];

// ---------------------------------------------------------------------------
// helpers
// ---------------------------------------------------------------------------
__device__ __forceinline__ uint32_t f2tf32(float x) {
    uint32_t r;
    asm("cvt.rna.tf32.f32 %0, %1;" : "=r"(r) : "f"(x));
    return r;
}

__device__ __forceinline__ uint32_t smem_u32(const void* p) {
    uint32_t a;
    asm("{ .reg .u64 t; cvta.to.shared.u64 t, %1; cvt.u32.u64 %0, t; }"
        : "=r"(a) : "l"(p));
    return a;
}

__device__ __forceinline__ void mma_sync_tf32(float* d, const uint32_t* a, const uint32_t* b) {
    asm volatile(
        "mma.sync.aligned.m16n8k8.row.col.f32.tf32.tf32.f32 "
        "{%0,%1,%2,%3}, {%4,%5,%6,%7}, {%8,%9}, {%0,%1,%2,%3};\n"
        : "+f"(d[0]), "+f"(d[1]), "+f"(d[2]), "+f"(d[3])
        : "r"(a[0]), "r"(a[1]), "r"(a[2]), "r"(a[3]), "r"(b[0]), "r"(b[1]));
}

__device__ __forceinline__ void ldm4(uint32_t* r, uint32_t saddr) {
    asm volatile(
        "ldmatrix.sync.aligned.m8n8.x4.shared.b16 {%0,%1,%2,%3}, [%4];"
        : "=r"(r[0]), "=r"(r[1]), "=r"(r[2]), "=r"(r[3])
        : "r"(saddr));
}

__device__ __forceinline__ void cp16(uint32_t dst, const void* src) {
    asm volatile("cp.async.cg.shared.global [%0], [%1], 16;"
                 :: "r"(dst), "l"(src) : "memory");
}
__device__ __forceinline__ void cp_commit() {
    asm volatile("cp.async.commit_group;" ::: "memory");
}
template<int N> __device__ __forceinline__ void cp_wait() {
    asm volatile("cp.async.wait_group %0;" :: "n"(N) : "memory");
}

// ---------------------------------------------------------------------------
// Stage 1: h = silu(layernorm(s @ W1^T + b1)), stored TRANSPOSED + tf32 bits
// ---------------------------------------------------------------------------
__global__ __launch_bounds__(256) void lin1_ln_silu_kernel(
    const float* __restrict__ s, const float* __restrict__ W1,
    const float* __restrict__ b1)
{
    __shared__ float smem[64 * 133];
    float* As = smem;                 // [64][36]
    float* Bs = smem + 64 * 36;       // [128][36]
    float* Hs = smem;                 // [64][133]

    const int tid  = threadIdx.x;
    const int r0   = blockIdx.x * 64;
    const int w    = tid >> 5;
    const int lane = tid & 31;
    const int g    = lane >> 2;
    const int tg   = lane & 3;
    const int wm   = w & 1;
    const int wn   = w >> 1;

    float acc[2][4][4];
    #pragma unroll
    for (int i = 0; i < 2; i++)
        #pragma unroll
        for (int j = 0; j < 4; j++)
            #pragma unroll
            for (int k = 0; k < 4; k++) acc[i][j][k] = 0.f;

    const uint32_t* A32 = (const uint32_t*)As;
    const uint32_t* B32 = (const uint32_t*)Bs;

    for (int kc = 0; kc < 4; kc++) {
        const int k0 = kc * 32;
        __syncthreads();
        #pragma unroll
        for (int it = 0; it < 2; it++) {
            int idx = tid + it * 256;
            int row = idx >> 3, q = idx & 7;
            float4 v = *(const float4*)(s + (size_t)(r0 + row) * HH + k0 + q * 4);
            uint32_t* dst = (uint32_t*)(As + row * 36 + q * 4);
            dst[0] = f2tf32(v.x); dst[1] = f2tf32(v.y);
            dst[2] = f2tf32(v.z); dst[3] = f2tf32(v.w);
        }
        #pragma unroll
        for (int it = 0; it < 4; it++) {
            int idx = tid + it * 256;
            int n = idx >> 3, q = idx & 7;
            float4 v = *(const float4*)(W1 + (size_t)n * HH + k0 + q * 4);
            uint32_t* dst = (uint32_t*)(Bs + n * 36 + q * 4);
            dst[0] = f2tf32(v.x); dst[1] = f2tf32(v.y);
            dst[2] = f2tf32(v.z); dst[3] = f2tf32(v.w);
        }
        __syncthreads();
        #pragma unroll
        for (int ks = 0; ks < 4; ks++) {
            const int kk = ks * 8;
            uint32_t af[2][4], bf[4][2];
            #pragma unroll
            for (int mt = 0; mt < 2; mt++) {
                int rm = wm * 32 + mt * 16;
                af[mt][0] = A32[(rm + g) * 36 + kk + tg];
                af[mt][1] = A32[(rm + g + 8) * 36 + kk + tg];
                af[mt][2] = A32[(rm + g) * 36 + kk + tg + 4];
                af[mt][3] = A32[(rm + g + 8) * 36 + kk + tg + 4];
            }
            #pragma unroll
            for (int nt = 0; nt < 4; nt++) {
                int cn = wn * 32 + nt * 8 + g;
                bf[nt][0] = B32[cn * 36 + kk + tg];
                bf[nt][1] = B32[cn * 36 + kk + tg + 4];
            }
            #pragma unroll
            for (int mt = 0; mt < 2; mt++)
                #pragma unroll
                for (int nt = 0; nt < 4; nt++)
                    mma_sync_tf32(acc[mt][nt], af[mt], bf[nt]);
        }
    }

    __syncthreads();
    #pragma unroll
    for (int mt = 0; mt < 2; mt++) {
        #pragma unroll
        for (int nt = 0; nt < 4; nt++) {
            int rm = wm * 32 + mt * 16 + g;
            int cn = wn * 32 + nt * 8 + 2 * tg;
            Hs[rm * 133 + cn]           = acc[mt][nt][0];
            Hs[rm * 133 + cn + 1]       = acc[mt][nt][1];
            Hs[(rm + 8) * 133 + cn]     = acc[mt][nt][2];
            Hs[(rm + 8) * 133 + cn + 1] = acc[mt][nt][3];
        }
    }
    __syncthreads();

    #pragma unroll
    for (int rr = 0; rr < 8; rr++) {
        int row = w * 8 + rr;
        float x[4];
        float sum = 0.f, sq = 0.f;
        #pragma unroll
        for (int k = 0; k < 4; k++) {
            float v = Hs[row * 133 + lane + 32 * k] + __ldg(b1 + lane + 32 * k);
            x[k] = v; sum += v; sq += v * v;
        }
        #pragma unroll
        for (int o = 16; o > 0; o >>= 1) {
            sum += __shfl_xor_sync(0xffffffffu, sum, o);
            sq  += __shfl_xor_sync(0xffffffffu, sq, o);
        }
        float mu  = sum * (1.f / 128.f);
        float var = sq * (1.f / 128.f) - mu * mu;
        float inv = rsqrtf(var + LN_EPS);
        #pragma unroll
        for (int k = 0; k < 4; k++) {
            float yv = (x[k] - mu) * inv;
            Hs[row * 133 + lane + 32 * k] = yv / (1.f + __expf(-yv));
        }
    }
    __syncthreads();

    // Transposed write-out as tf32 bits: g_hT[b][d][n]
    const int b  = r0 >> 9;
    const int n0 = r0 & 511;
    #pragma unroll
    for (int it = 0; it < 8; it++) {
        int idx = tid + it * 256;
        int d = idx >> 4;
        int q = idx & 15;
        uint4 v;
        v.x = f2tf32(Hs[(q * 4 + 0) * 133 + d]);
        v.y = f2tf32(Hs[(q * 4 + 1) * 133 + d]);
        v.z = f2tf32(Hs[(q * 4 + 2) * 133 + d]);
        v.w = f2tf32(Hs[(q * 4 + 3) * 133 + d]);
        *(uint4*)(g_hT + ((size_t)b * HH + d) * NN + n0 + q * 4) = v;
    }
}

// ---------------------------------------------------------------------------
// Stage 2: mma.sync tf32 GEMM with cp.async 3-deep pipeline.
// Block: batch b, m-tile 128 (m=i*3+c), N=128 (d), K=512 (j) in 16 chunks of 32.
// 512 threads = 16 warps (4x4 grid), warp tile 32m x 32n, acc 32 regs.
// Smem: A[2][128][36] tf32 | B ring[3] swizzled | ev raw ring[3] | mask ring[3].
// ---------------------------------------------------------------------------
#define AST 36
#define OFF_A0 0u
#define OFF_A1 18432u
#define OFF_B  36864u      /* + r*16384 */
#define OFF_EV 86016u      /* + r*16896 */
#define OFF_MK 136704u     /* + r*5632  */
#define SMEM2  153600

__global__ __launch_bounds__(512, 1)
void cfconv3_kernel(const float* __restrict__ ev,
                    const float* __restrict__ mask,
                    float* __restrict__ out)
{
    extern __shared__ __align__(16) char smemc[];
    const uint32_t sb = smem_u32(smemc);

    const int tid  = threadIdx.x;
    const int w    = tid >> 5;
    const int lane = tid & 31;
    const int g    = lane >> 2;
    const int tg   = lane & 3;
    const int wm   = w & 3;       // 4 warp rows (32 m each)
    const int wn   = w >> 2;      // 4 warp cols (32 n each)

    const int b    = blockIdx.y;
    const int m0   = blockIdx.x * 128;
    const int i_lo = m0 / 3;
    const int i_hi = (m0 + 127) / 3;
    const int icnt = i_hi - i_lo + 1;     // <= 44

    const float*    evB   = ev   + (((size_t)b * NN) * NN) * 3;
    const float*    maskB = mask + ((size_t)b * NN) * NN;
    const uint32_t* hTB   = g_hT + ((size_t)b * HH) * NN;

    // ldmatrix per-lane constants (mappings verbatim from verified R3 kernel)
    const int arow  = (lane & 7) + ((lane >> 3) & 1) * 8;
    const int ahalf = (lane >> 4) & 1;
    const uint32_t aoff = (uint32_t)(((wm * 32 + arow) * AST + ahalf * 4) * 4);
    const int brow  = (lane & 7) + ((lane >> 4) & 1) * 8;
    const int bhalf = (lane >> 3) & 1;
    const int l7    = lane & 7;

    float acc[2][4][4];
    #pragma unroll
    for (int mt = 0; mt < 2; mt++)
        #pragma unroll
        for (int nt = 0; nt < 4; nt++)
            #pragma unroll
            for (int k = 0; k < 4; k++) acc[mt][nt][k] = 0.f;

    // ---- issue cp.async group for chunk ch ----
    auto issue = [&](int ch) {
        const int r  = ch % 3;
        const int j0 = ch * 32;
        // B tile: h_T tf32, 128d x 32j, swizzled 128B rows. 1024 chunks.
        const uint32_t bb = sb + OFF_B + (uint32_t)r * 16384u;
        #pragma unroll
        for (int it = 0; it < 2; it++) {
            int idx = tid + it * 512;
            int d = idx >> 3, q = idx & 7;
            cp16(bb + (uint32_t)(d * 128 + ((q ^ (d & 7)) << 4)),
                 hTB + (size_t)d * NN + j0 + q * 4);
        }
        // ev raw: icnt rows x 96 floats, contiguous.
        const uint32_t eb = sb + OFF_EV + (uint32_t)r * 16896u;
        #pragma unroll
        for (int it = 0; it < 3; it++) {
            int idx = tid + it * 512;
            if (idx < icnt * 24) {
                int rr = idx / 24, q = idx - rr * 24;
                cp16(eb + (uint32_t)idx * 16u,
                     evB + ((size_t)(i_lo + rr) * NN + j0) * 3 + q * 4);
            }
        }
        // mask raw: icnt rows x 32 floats.
        {
            int idx = tid;
            if (idx < icnt * 8) {
                cp16(sb + OFF_MK + (uint32_t)r * 5632u + (uint32_t)idx * 16u,
                     maskB + (size_t)(i_lo + (idx >> 3)) * NN + j0 + (idx & 7) * 4);
            }
        }
        cp_commit();
    };

    // ---- build A[p] (mask*ev -> tf32) from raw ring slot of chunk ch ----
    auto buildA = [&](int p, int ch) {
        const int r = ch % 3;
        const float* evr = (const float*)(smemc + OFF_EV + (size_t)r * 16896u);
        const float* mkr = (const float*)(smemc + OFF_MK + (size_t)r * 5632u);
        uint32_t* Ab = (uint32_t*)(smemc + (p ? OFF_A1 : OFF_A0));
        #pragma unroll
        for (int it = 0; it < 3; it++) {
            int idx = tid + it * 512;
            if (idx < icnt * 24) {
                int rr = idx / 24, q = idx - rr * 24;
                float4 v = *(const float4*)(evr + idx * 4);
                int jc0 = q * 4, ja = jc0 / 3;
                float mA = mkr[rr * 32 + ja];
                float mB2 = mkr[rr * 32 + ja + 1];
                int mbase = (i_lo + rr) * 3 - m0;
                float fv[4] = {v.x, v.y, v.z, v.w};
                #pragma unroll
                for (int e = 0; e < 4; e++) {
                    int jc = jc0 + e;
                    int jl = jc / 3, c = jc - 3 * jl;
                    int m = mbase + c;
                    if (m >= 0 && m < 128)
                        Ab[m * AST + jl] = f2tf32(fv[e] * (jl == ja ? mA : mB2));
                }
            }
        }
    };

    // Prologue: 3 chunks in flight, build A0.
    issue(0); issue(1); issue(2);
    cp_wait<2>();
    __syncthreads();
    buildA(0, 0);
    __syncthreads();

    for (int ch = 0; ch < 16; ch++) {
        const int p = ch & 1;
        const uint32_t Ab = sb + (p ? OFF_A1 : OFF_A0);
        const uint32_t Bb = sb + OFF_B + (uint32_t)(ch % 3) * 16384u;

        // MMA over A[p] and swizzled B ring slot
        #pragma unroll
        for (int ks = 0; ks < 4; ks++) {
            uint32_t af[2][4], bf[2][4];
            #pragma unroll
            for (int mt = 0; mt < 2; mt++)
                ldm4(af[mt], Ab + aoff + (uint32_t)(mt * 16 * AST * 4 + ks * 32));
            #pragma unroll
            for (int bt = 0; bt < 2; bt++) {
                int n = wn * 32 + bt * 16 + brow;
                ldm4(bf[bt], Bb + (uint32_t)(n * 128 + (((ks * 2 + bhalf) ^ l7) << 4)));
            }
            #pragma unroll
            for (int mt = 0; mt < 2; mt++)
                #pragma unroll
                for (int nt = 0; nt < 4; nt++)
                    mma_sync_tf32(acc[mt][nt], af[mt], &bf[nt >> 1][(nt & 1) * 2]);
        }

        if (ch < 14)       cp_wait<1>();
        else if (ch == 14) cp_wait<0>();
        __syncthreads();

        if (ch < 15) {
            buildA(p ^ 1, ch + 1);
            if (ch <= 12) issue(ch + 3);
        }
        __syncthreads();
    }

    // Epilogue
    const size_t obase = ((size_t)b * 1536 + m0) * HH;
    #pragma unroll
    for (int mt = 0; mt < 2; mt++) {
        #pragma unroll
        for (int nt = 0; nt < 4; nt++) {
            int m  = wm * 32 + mt * 16 + g;
            int cn = wn * 32 + nt * 8 + 2 * tg;
            *(float2*)(out + obase + (size_t)m * HH + cn) =
                make_float2(acc[mt][nt][0], acc[mt][nt][1]);
            *(float2*)(out + obase + (size_t)(m + 8) * HH + cn) =
                make_float2(acc[mt][nt][2], acc[mt][nt][3]);
        }
    }
}

// ---------------------------------------------------------------------------
// Launch
// ---------------------------------------------------------------------------
extern "C" void kernel_launch(void* const* d_in, const int* in_sizes, int n_in,
                              void* d_out, int out_size) {
    (void)in_sizes; (void)n_in; (void)out_size;
    const float* s    = (const float*)d_in[0];
    const float* ev   = (const float*)d_in[1];
    const float* mask = (const float*)d_in[2];
    const float* W1   = (const float*)d_in[3];
    const float* b1   = (const float*)d_in[4];
    float* out = (float*)d_out;

    cudaFuncSetAttribute(cfconv3_kernel,
                         cudaFuncAttributeMaxDynamicSharedMemorySize, SMEM2);

    lin1_ln_silu_kernel<<<256, 256>>>(s, W1, b1);
    cfconv3_kernel<<<dim3(12, 32), 512, SMEM2>>>(ev, mask, out);
}